// round 1
// baseline (speedup 1.0000x reference)
#include <cuda_runtime.h>
#include <cstdint>

// ---------------------------------------------------------------------------
// Wav2Vec2 Gumbel VQ (inference path):
//   logits = h @ W + b           h:[BT=65536, 512]  W:[512, 640]
//   idx    = argmax per (token, group of 320)
//   out[t] = concat(cb[0, idx0], cb[1, idx1])   (256 floats per token)
//   perplexity scalar from the count histogram  -> d_out[out_size-1]
// ---------------------------------------------------------------------------

namespace {
constexpr int kBT      = 65536;   // B*S tokens
constexpr int kH       = 512;     // hidden dim (K of GEMM)
constexpr int kGV      = 640;     // G*V logits per token
constexpr int kV       = 320;     // codes per group
constexpr int kBM      = 64;      // tokens per CTA
constexpr int kThreads = 256;
constexpr int kNC      = 32;      // logit columns per chunk
constexpr int kNChunks = kGV / kNC;          // 20 (0..9 group0, 10..19 group1)
constexpr int kHS      = kH + 4;  // smem row stride (floats) for h  (516)
constexpr int kWS      = kH + 4;  // smem row stride (floats) for w^T (516)
constexpr int kSmemBytes = (kBM * kHS + kNC * kWS) * 4;   // 198144 B
}  // namespace

__device__ int g_counts[kGV];

// packed f32x2 FMA: acc.{lo,hi} += a.{lo,hi} * b.{lo,hi}
__device__ __forceinline__ void fma2(unsigned long long& acc,
                                     unsigned long long a,
                                     unsigned long long b) {
    asm("fma.rn.f32x2 %0, %1, %2, %0;" : "+l"(acc) : "l"(a), "l"(b));
}

__device__ __forceinline__ float pairsum(unsigned long long a) {
    float lo = __uint_as_float((unsigned int)a);
    float hi = __uint_as_float((unsigned int)(a >> 32));
    return lo + hi;
}

__global__ void __launch_bounds__(kThreads, 1)
vq_main(const float* __restrict__ hid,   // [BT, 512]
        const float* __restrict__ W,     // [512, 640]
        const float* __restrict__ bias,  // [640]
        const float* __restrict__ cb,    // [640, 128]
        float* __restrict__ out)         // [BT, 256]
{
    extern __shared__ float smem[];
    float* h_s = smem;                 // [kBM][kHS]
    float* w_s = smem + kBM * kHS;     // [kNC][kWS]  (W chunk, transposed)

    const int tid = threadIdx.x;
    const int m0  = blockIdx.x * kBM;

    // ---- load h tile (64 x 512 fp32, coalesced float4) ----
    {
        const float4* hg = (const float4*)(hid + (size_t)m0 * kH);
        for (int e = tid; e < kBM * (kH / 4); e += kThreads) {
            int m  = e >> 7;        // /128
            int k4 = e & 127;
            float4 v = hg[(size_t)m * (kH / 4) + k4];
            *(float4*)(h_s + m * kHS + k4 * 4) = v;
        }
    }

    const int tn = tid & 15;           // 16 n-threads (2 cols each)
    const int tm = tid >> 4;           // 16 m-threads (4 rows each)
    const int mb = tm * 4;

    const int lane   = tid & 31;
    const int warp   = tid >> 5;
    const int nlo    = lane & 7;       // W-chunk loader mapping
    const int kq_off = lane >> 3;

    float bmax[4], g0max[4];
    int   bidx[4], g0idx[4];
#pragma unroll
    for (int i = 0; i < 4; i++) { bmax[i] = -3.4e38f; bidx[i] = 0;
                                  g0max[i] = -3.4e38f; g0idx[i] = 0; }

    const ulonglong2* hu[4];
#pragma unroll
    for (int i = 0; i < 4; i++)
        hu[i] = (const ulonglong2*)(h_s + (mb + i) * kHS);

    for (int c = 0; c < kNChunks; c++) {
        const int n0 = c * kNC;

        // ---- stage W[:, n0:n0+32] transposed into w_s[n][k] ----
        // per-warp: 8 n-values x 4 k-values -> conflict-free STS, 4x32B LDG
#pragma unroll 4
        for (int j = 0; j < 64; j++) {
            int q    = warp + (j << 3);     // 0..511
            int nhi  = q & 3;
            int kblk = q >> 2;              // 0..127
            int k    = (kblk << 2) + kq_off;
            int nl   = (nhi << 3) + nlo;
            w_s[nl * kWS + k] = W[(size_t)k * kGV + (n0 + nl)];
        }
        __syncthreads();

        // ---- 64x32x512 fp32 GEMM chunk via packed f32x2 FMA ----
        unsigned long long acc[4][2];
#pragma unroll
        for (int i = 0; i < 4; i++) { acc[i][0] = 0ull; acc[i][1] = 0ull; }

        const ulonglong2* wu0 = (const ulonglong2*)(w_s + (2 * tn) * kWS);
        const ulonglong2* wu1 = (const ulonglong2*)(w_s + (2 * tn + 1) * kWS);

#pragma unroll 4
        for (int kk = 0; kk < kH / 4; kk++) {
            ulonglong2 w0 = wu0[kk];
            ulonglong2 w1 = wu1[kk];
#pragma unroll
            for (int i = 0; i < 4; i++) {
                ulonglong2 h = hu[i][kk];
                fma2(acc[i][0], h.x, w0.x);
                fma2(acc[i][0], h.y, w0.y);
                fma2(acc[i][1], h.x, w1.x);
                fma2(acc[i][1], h.y, w1.y);
            }
        }

        // ---- fold + running argmax ----
        const float b0 = bias[n0 + 2 * tn];
        const float b1 = bias[n0 + 2 * tn + 1];
        const int   nbase = n0 + 2 * tn - ((c >= 10) ? kV : 0);
#pragma unroll
        for (int i = 0; i < 4; i++) {
            float v0 = pairsum(acc[i][0]) + b0;
            float v1 = pairsum(acc[i][1]) + b1;
            if (v0 > bmax[i]) { bmax[i] = v0; bidx[i] = nbase; }
            if (v1 > bmax[i]) { bmax[i] = v1; bidx[i] = nbase + 1; }
        }
        if (c == 9) {
#pragma unroll
            for (int i = 0; i < 4; i++) {
                g0max[i] = bmax[i]; g0idx[i] = bidx[i];
                bmax[i] = -3.4e38f; bidx[i] = 0;
            }
        }
        __syncthreads();   // w_s rewritten next chunk
    }

    // ---- cross-thread argmax reduction (reuse w_s as scratch) ----
    float* rmax  = w_s;                       // [2][64][16] floats
    int*   ridx  = (int*)(w_s + 2048);        // [2][64][16] ints
    int*   idx_s = (int*)(w_s + 4096);        // [64][2] ints
#pragma unroll
    for (int i = 0; i < 4; i++) {
        int m = mb + i;
        rmax[m * 16 + tn]        = g0max[i];
        ridx[m * 16 + tn]        = g0idx[i];
        rmax[1024 + m * 16 + tn] = bmax[i];
        ridx[1024 + m * 16 + tn] = bidx[i];
    }
    __syncthreads();

    if (tid < 128) {
        int g = tid >> 6;
        int m = tid & 63;
        int base = g * 1024 + m * 16;
        float best = -3.4e38f; int bi = 0x7fffffff;
#pragma unroll
        for (int t = 0; t < 16; t++) {
            float v = rmax[base + t];
            int   id = ridx[base + t];
            if (v > best || (v == best && id < bi)) { best = v; bi = id; }
        }
        atomicAdd(&g_counts[g * kV + bi], 1);
        idx_s[(m << 1) | g] = bi;
    }
    __syncthreads();

    // ---- gather codevectors, coalesced float4 writes ----
    const float4* cbv  = (const float4*)cb;   // 640 rows x 32 float4
    float4*       outv = (float4*)out;
    for (int e = tid; e < kBM * 64; e += kThreads) {
        int m = e >> 6;
        int q = e & 63;            // 0..63 float4 within the 256-float row
        int g = q >> 5;
        int j = q & 31;
        int vi = idx_s[(m << 1) | g];
        outv[(size_t)(m0 + m) * 64 + q] = cbv[(size_t)(g * kV + vi) * 32 + j];
    }
}

__global__ void vq_zero() {
    if (threadIdx.x < kGV) g_counts[threadIdx.x] = 0;
}

__global__ void vq_ppl(float* __restrict__ out, int out_size) {
    __shared__ float terms[2 * kV];
    int t = threadIdx.x;               // 320 threads
    for (int g = 0; g < 2; g++) {
        float m = (float)g_counts[g * kV + t] / (float)kBT;
        terms[g * kV + t] = m * logf(m + 1e-7f);
    }
    __syncthreads();
    if (t == 0) {
        float p = 0.f;
        for (int g = 0; g < 2; g++) {
            float s = 0.f;
            for (int v = 0; v < kV; v++) s += terms[g * kV + v];
            p += expf(-s);
        }
        out[out_size - 1] = p;
    }
}

extern "C" void kernel_launch(void* const* d_in, const int* in_sizes, int n_in,
                              void* d_out, int out_size) {
    (void)in_sizes; (void)n_in;
    const float* hid  = (const float*)d_in[0];
    const float* W    = (const float*)d_in[1];
    const float* bias = (const float*)d_in[2];
    const float* cb   = (const float*)d_in[3];
    float* out = (float*)d_out;

    cudaFuncSetAttribute(vq_main, cudaFuncAttributeMaxDynamicSharedMemorySize,
                         kSmemBytes);

    vq_zero<<<1, kGV>>>();
    vq_main<<<kBT / kBM, kThreads, kSmemBytes>>>(hid, W, bias, cb, out);
    vq_ppl<<<1, kV>>>(out, out_size);
}